// round 6
// baseline (speedup 1.0000x reference)
#include <cuda_runtime.h>
#include <cuda_bf16.h>
#include <cstdint>

#define D 128
#define NMAX 100000
#define EMAX 600000

// ---------------- scratch (static __device__, no allocations) ----------------
__device__ float g_part[NMAX * D];           // fp32 partial (acc pairs)
__device__ __nv_bfloat16 g_sb[NMAX * 256];   // src_emb  [hi|lo]
__device__ __nv_bfloat16 g_hb0[NMAX * 256];
__device__ __nv_bfloat16 g_hb1[NMAX * 256];
__device__ __nv_bfloat16 g_hb2[NMAX * 256];
__device__ __nv_bfloat16 g_hb3[NMAX * 256];
__device__ __nv_bfloat16 g_mbb[NMAX * 256];  // mean agg / pre-cand1
__device__ __nv_bfloat16 g_xbb[NMAX * 256];  // max agg  / pre-cand2
__device__ __nv_bfloat16 g_wb[27 * 32768];   // transposed weights [f][hi d|lo d]
__device__ int   g_deg[NMAX];
__device__ int   g_off[NMAX + 1];
__device__ int   g_pos[NMAX];
__device__ int   g_csr[EMAX];
__device__ float g_stats2[9 * 768];
__device__ float g_coef2[9 * 768];

// chunk-step tables: 6 steps per candidate, B-reuse ordered
__constant__ int c_aoffs[6] = {0, 256, 128, 384, 0, 128};
__constant__ int c_boffs[6] = {0, 0, 128, 128, 256, 384};
__constant__ int c_bnew[6]  = {1, 0, 1, 0, 1, 1};

// ================= helpers =================
__device__ __forceinline__ uint32_t smem_u32(const void* p) {
    uint32_t a;
    asm("{ .reg .u64 t; cvta.to.shared.u64 t, %1; cvt.u32.u64 %0, t; }" : "=r"(a) : "l"(p));
    return a;
}
__device__ __forceinline__ void ldsm4(uint32_t addr, uint32_t* r) {
    asm volatile("ldmatrix.sync.aligned.m8n8.x4.shared.b16 {%0,%1,%2,%3}, [%4];"
                 : "=r"(r[0]), "=r"(r[1]), "=r"(r[2]), "=r"(r[3]) : "r"(addr));
}
__device__ __forceinline__ void mma16816(float* c, const uint32_t* a, uint32_t b0,
                                         uint32_t b1) {
    asm volatile(
        "mma.sync.aligned.m16n8k16.row.col.f32.bf16.bf16.f32 "
        "{%0,%1,%2,%3}, {%4,%5,%6,%7}, {%8,%9}, {%0,%1,%2,%3};"
        : "+f"(c[0]), "+f"(c[1]), "+f"(c[2]), "+f"(c[3])
        : "r"(a[0]), "r"(a[1]), "r"(a[2]), "r"(a[3]), "r"(b0), "r"(b1));
}
__device__ __forceinline__ void cpa16(uint32_t dst, const void* src, uint32_t sz) {
    asm volatile("cp.async.cg.shared.global [%0], [%1], 16, %2;" ::"r"(dst), "l"(src),
                 "r"(sz));
}
#define CPCOMMIT() asm volatile("cp.async.commit_group;" ::: "memory")
template <int N>
__device__ __forceinline__ void cpwait() {
    asm volatile("cp.async.wait_group %0;" ::"n"(N) : "memory");
}
__device__ __forceinline__ uint32_t b2u(__nv_bfloat162 v) {
    return *reinterpret_cast<uint32_t*>(&v);
}
__device__ __forceinline__ void split2(float2 p, uint32_t& hi, uint32_t& lo) {
    __nv_bfloat162 h = __float22bfloat162_rn(p);
    float2 hb = __bfloat1622float2(h);
    float2 r = make_float2(p.x - hb.x, p.y - hb.y);
    __nv_bfloat162 l = __float22bfloat162_rn(r);
    hi = b2u(h);
    lo = b2u(l);
}
__device__ __forceinline__ void write4(__nv_bfloat16* buf, int row, int col, float4 v) {
    uint32_t h0, l0, h1, l1;
    split2(make_float2(v.x, v.y), h0, l0);
    split2(make_float2(v.z, v.w), h1, l1);
    *reinterpret_cast<uint2*>(buf + (size_t)row * 256 + col) = make_uint2(h0, h1);
    *reinterpret_cast<uint2*>(buf + (size_t)row * 256 + 128 + col) = make_uint2(l0, l1);
}

// smem: A0 @0, A1 @18432, B0 @36864, B1 @55296, csum @73728, csq @74240
#define STG 18432
#define SM_CS 73728
#define SMEM_BYTES 74752

__device__ __forceinline__ void loadA(uint32_t sdst, const char* xb, int row0, int n,
                                      int aoff, int t) {
#pragma unroll
    for (int i = 0; i < 2; i++) {
        int idx = t + i * 512;
        int row = idx >> 3, c = idx & 7;
        int gr = row0 + row;
        uint32_t sz = gr < n ? 16u : 0u;
        int gc = gr < n ? gr : 0;
        cpa16(sdst + row * 144 + c * 16, xb + (size_t)gc * 512 + aoff + c * 16, sz);
    }
}
__device__ __forceinline__ void loadB(uint32_t sdst, const char* wmat, int boff, int t) {
#pragma unroll
    for (int i = 0; i < 2; i++) {
        int idx = t + i * 512;
        int row = idx >> 3, c = idx & 7;
        cpa16(sdst + row * 144 + c * 16, wmat + (size_t)row * 512 + boff + c * 16, 16u);
    }
}

__device__ __forceinline__ void compute_chunk(uint32_t sA, uint32_t sB, float acc[2][4][4],
                                              int wm, int wn, int lane) {
    uint32_t a_base = sA + (uint32_t)(wm * 32 + (lane & 15)) * 144 + (uint32_t)(lane >> 4) * 16;
    uint32_t b_base = sB + (uint32_t)(wn * 32 + (lane & 15)) * 144 + (uint32_t)(lane >> 4) * 16;
#pragma unroll
    for (int ks = 0; ks < 4; ks++) {
        uint32_t kb = (uint32_t)ks * 32;
        uint32_t a0[4], a1[4], b0[4], b1[4];
        ldsm4(a_base + kb, a0);
        ldsm4(a_base + 16 * 144 + kb, a1);
        ldsm4(b_base + kb, b0);
        ldsm4(b_base + 16 * 144 + kb, b1);
#pragma unroll
        for (int nt = 0; nt < 4; nt++) {
            uint32_t x0 = (nt & 2) ? b1[nt & 1] : b0[nt & 1];
            uint32_t x1 = (nt & 2) ? b1[(nt & 1) + 2] : b0[(nt & 1) + 2];
            mma16816(acc[0][nt], a0, x0, x1);
            mma16816(acc[1][nt], a1, x0, x1);
        }
    }
}

// ---------------- pass1: GEMM -> column stats only ----------------
__global__ void __launch_bounds__(512) gemm_p1(
    const __nv_bfloat16* __restrict__ xa, const __nv_bfloat16* __restrict__ xbp,
    const __nv_bfloat16* __restrict__ xc, const __nv_bfloat16* __restrict__ wmat,
    const float* __restrict__ bias, float* __restrict__ stats, int n, int multi,
    int nsteps) {
    extern __shared__ char sc[];
    uint32_t sb = smem_u32(sc);
    float* csum = (float*)(sc + SM_CS);
    float* csq = csum + 128;
    const int t = threadIdx.x;
    const int wid = t >> 5, lane = t & 31;
    const int wm = wid & 3, wn = wid >> 2;
    const int row0 = blockIdx.x * 128;

    const __nv_bfloat16* xs[3] = {xa, xbp, xc};
    if (!multi) {
        int cy = blockIdx.y;
        const __nv_bfloat16* xx = cy == 0 ? xa : (cy == 1 ? xbp : xc);
        xs[0] = xs[1] = xs[2] = xx;
        wmat += (size_t)cy * 32768;
        bias += cy * 128;
        stats += cy * 256;
    }
    if (t < 128) { csum[t] = 0.f; csq[t] = 0.f; }

    float acc[2][4][4];
#pragma unroll
    for (int i = 0; i < 2; i++)
#pragma unroll
        for (int j = 0; j < 4; j++)
#pragma unroll
            for (int q = 0; q < 4; q++) acc[i][j][q] = 0.f;

    loadA(sb, (const char*)xs[0], row0, n, c_aoffs[0], t);
    loadB(sb + 36864, (const char*)wmat, c_boffs[0], t);
    CPCOMMIT();
    int bld = 1;
    for (int s = 0; s < nsteps; s++) {
        if (s + 1 < nsteps) {
            int s1 = s + 1, c1 = s1 / 6, u1 = s1 % 6;
            loadA(sb + (uint32_t)((s1 & 1) * STG), (const char*)xs[c1], row0, n, c_aoffs[u1],
                  t);
            if (c_bnew[u1]) {
                loadB(sb + 36864 + (uint32_t)((bld & 1) * STG),
                      (const char*)wmat + (size_t)c1 * 65536, c_boffs[u1], t);
                bld++;
            }
            CPCOMMIT();
            cpwait<1>();
        } else {
            CPCOMMIT();
            cpwait<0>();
        }
        __syncthreads();
        int cs = s / 6, us = s % 6;
        int bi = cs * 4 + (us < 2 ? 0 : (us < 4 ? 1 : us - 2));
        compute_chunk(sb + (uint32_t)((s & 1) * STG), sb + 36864 + (uint32_t)((bi & 1) * STG),
                      acc, wm, wn, lane);
        __syncthreads();
    }

    // stats epilogue
    float ps[4][2], pq[4][2];
#pragma unroll
    for (int nt = 0; nt < 4; nt++) {
        ps[nt][0] = 0.f; ps[nt][1] = 0.f; pq[nt][0] = 0.f; pq[nt][1] = 0.f;
    }
    int mrow = row0 + wm * 32 + (lane >> 2);
#pragma unroll
    for (int mt = 0; mt < 2; mt++)
#pragma unroll
        for (int h = 0; h < 2; h++) {
            int r = mrow + mt * 16 + h * 8;
            bool ok = r < n;
#pragma unroll
            for (int nt = 0; nt < 4; nt++) {
                int col = wn * 32 + nt * 8 + (lane & 3) * 2;
                float v0 = acc[mt][nt][h * 2 + 0] + __ldg(bias + col);
                float v1 = acc[mt][nt][h * 2 + 1] + __ldg(bias + col + 1);
                if (ok) {
                    ps[nt][0] += v0; pq[nt][0] += v0 * v0;
                    ps[nt][1] += v1; pq[nt][1] += v1 * v1;
                }
            }
        }
#pragma unroll
    for (int off = 16; off >= 4; off >>= 1)
#pragma unroll
        for (int nt = 0; nt < 4; nt++) {
            ps[nt][0] += __shfl_xor_sync(0xffffffffu, ps[nt][0], off);
            ps[nt][1] += __shfl_xor_sync(0xffffffffu, ps[nt][1], off);
            pq[nt][0] += __shfl_xor_sync(0xffffffffu, pq[nt][0], off);
            pq[nt][1] += __shfl_xor_sync(0xffffffffu, pq[nt][1], off);
        }
    if ((lane >> 2) == 0) {
#pragma unroll
        for (int nt = 0; nt < 4; nt++) {
            int col = wn * 32 + nt * 8 + (lane & 3) * 2;
            atomicAdd(&csum[col], ps[nt][0]);
            atomicAdd(&csum[col + 1], ps[nt][1]);
            atomicAdd(&csq[col], pq[nt][0]);
            atomicAdd(&csq[col + 1], pq[nt][1]);
        }
    }
    __syncthreads();
    if (t < 128) {
        atomicAdd(&stats[t], csum[t]);
        atomicAdd(&stats[128 + t], csq[t]);
    }
}

// ---------------- pass2: recompute GEMM + fused affine/relu/combine ----------------
__device__ __forceinline__ void transform(float acc[2][4][4], float out[2][4][4],
                                          const float* __restrict__ coefr, int nk, int cand,
                                          const float* __restrict__ biasc, float w, int wn,
                                          int lane) {
#pragma unroll
    for (int nt = 0; nt < 4; nt++) {
        int col = wn * 32 + nt * 8 + (lane & 3) * 2;
        float a0 = __ldg(coefr + cand * 128 + col);
        float a1 = __ldg(coefr + cand * 128 + col + 1);
        float cc0 = __ldg(coefr + nk * 128 + cand * 128 + col);
        float cc1 = __ldg(coefr + nk * 128 + cand * 128 + col + 1);
        float b0 = __ldg(biasc + col);
        float b1 = __ldg(biasc + col + 1);
#pragma unroll
        for (int mt = 0; mt < 2; mt++)
#pragma unroll
            for (int h = 0; h < 2; h++) {
                float v0 = fmaxf(fmaf(a0, acc[mt][nt][h * 2 + 0] + b0, cc0), 0.f);
                float v1 = fmaxf(fmaf(a1, acc[mt][nt][h * 2 + 1] + b1, cc1), 0.f);
                out[mt][nt][h * 2 + 0] += w * v0;
                out[mt][nt][h * 2 + 1] += w * v1;
                acc[mt][nt][h * 2 + 0] = 0.f;
                acc[mt][nt][h * 2 + 1] = 0.f;
            }
    }
}

__global__ void __launch_bounds__(512) gemm_p2(
    const __nv_bfloat16* __restrict__ xa, const __nv_bfloat16* __restrict__ xbp,
    const __nv_bfloat16* __restrict__ xc, const __nv_bfloat16* __restrict__ wmat,
    const float* __restrict__ bias, const float* __restrict__ coefr,
    const float* __restrict__ wv, const float* __restrict__ accin, float* __restrict__ hout,
    __nv_bfloat16* __restrict__ hbout, int n, int nsteps, int fuse3, int nk) {
    extern __shared__ char sc[];
    uint32_t sb = smem_u32(sc);
    const int t = threadIdx.x;
    const int wid = t >> 5, lane = t & 31;
    const int wm = wid & 3, wn = wid >> 2;
    const int row0 = blockIdx.x * 128;
    const __nv_bfloat16* xs[3] = {xa, xbp, xc};

    float acc[2][4][4], out[2][4][4];
#pragma unroll
    for (int i = 0; i < 2; i++)
#pragma unroll
        for (int j = 0; j < 4; j++)
#pragma unroll
            for (int q = 0; q < 4; q++) { acc[i][j][q] = 0.f; out[i][j][q] = 0.f; }

    loadA(sb, (const char*)xs[0], row0, n, c_aoffs[0], t);
    loadB(sb + 36864, (const char*)wmat, c_boffs[0], t);
    CPCOMMIT();
    int bld = 1;
    for (int s = 0; s < nsteps; s++) {
        if (s + 1 < nsteps) {
            int s1 = s + 1, c1 = s1 / 6, u1 = s1 % 6;
            loadA(sb + (uint32_t)((s1 & 1) * STG), (const char*)xs[c1], row0, n, c_aoffs[u1],
                  t);
            if (c_bnew[u1]) {
                loadB(sb + 36864 + (uint32_t)((bld & 1) * STG),
                      (const char*)wmat + (size_t)c1 * 65536, c_boffs[u1], t);
                bld++;
            }
            CPCOMMIT();
            cpwait<1>();
        } else {
            CPCOMMIT();
            cpwait<0>();
        }
        __syncthreads();
        int cs = s / 6, us = s % 6;
        int bi = cs * 4 + (us < 2 ? 0 : (us < 4 ? 1 : us - 2));
        compute_chunk(sb + (uint32_t)((s & 1) * STG), sb + 36864 + (uint32_t)((bi & 1) * STG),
                      acc, wm, wn, lane);
        __syncthreads();
        if (fuse3 && us == 5)
            transform(acc, out, coefr, nk, cs, bias + cs * 128, __ldg(wv + cs), wn, lane);
    }
    if (!fuse3) transform(acc, out, coefr, nk, 0, bias, 1.0f, wn, lane);

    // write epilogue
    int mrow = row0 + wm * 32 + (lane >> 2);
    uint32_t* hp = (uint32_t*)hbout;
#pragma unroll
    for (int mt = 0; mt < 2; mt++)
#pragma unroll
        for (int h = 0; h < 2; h++) {
            int r = mrow + mt * 16 + h * 8;
            if (r >= n) continue;
#pragma unroll
            for (int nt = 0; nt < 4; nt++) {
                int col = wn * 32 + nt * 8 + (lane & 3) * 2;
                float v0 = out[mt][nt][h * 2 + 0];
                float v1 = out[mt][nt][h * 2 + 1];
                if (accin) {
                    float2 p = *(const float2*)(accin + (size_t)r * 128 + col);
                    v0 += p.x; v1 += p.y;
                }
                if (hout) *(float2*)(hout + (size_t)r * 128 + col) = make_float2(v0, v1);
                if (hbout) {
                    uint32_t hi, lo;
                    split2(make_float2(v0, v1), hi, lo);
                    hp[(size_t)r * 128 + (col >> 1)] = hi;
                    hp[(size_t)r * 128 + 64 + (col >> 1)] = lo;
                }
            }
        }
}

// ---------------- weight pre-conversion ----------------
__global__ void convw_kernel(const float* __restrict__ W, __nv_bfloat16* __restrict__ dst) {
    int bm = blockIdx.x;
    const float* Wk = W + (size_t)bm * 16384;
    __nv_bfloat16* ob = dst + (size_t)bm * 32768;
    int t = threadIdx.x;
    int f = t & 127;
    int d0 = (t >> 7) * 64;
#pragma unroll 4
    for (int jd = 0; jd < 64; jd += 4) {
        int d = d0 + jd;
        float w0 = Wk[(size_t)(d + 0) * D + f];
        float w1 = Wk[(size_t)(d + 1) * D + f];
        float w2 = Wk[(size_t)(d + 2) * D + f];
        float w3 = Wk[(size_t)(d + 3) * D + f];
        uint32_t h0, l0, h1, l1;
        split2(make_float2(w0, w1), h0, l0);
        split2(make_float2(w2, w3), h1, l1);
        *reinterpret_cast<uint2*>(ob + (size_t)f * 256 + d) = make_uint2(h0, h1);
        *reinterpret_cast<uint2*>(ob + (size_t)f * 256 + 128 + d) = make_uint2(l0, l1);
    }
}

// ---------------- small utility kernels ----------------
__global__ void zerof_kernel(float* p, int nel) {
    int i = blockIdx.x * blockDim.x + threadIdx.x;
    if (i < nel) p[i] = 0.f;
}
__global__ void zeroi_kernel(int* p, int nel) {
    int i = blockIdx.x * blockDim.x + threadIdx.x;
    if (i < nel) p[i] = 0;
}
__global__ void copyi_kernel(const int* __restrict__ a, int* __restrict__ b, int nel) {
    int i = blockIdx.x * blockDim.x + threadIdx.x;
    if (i < nel) b[i] = a[i];
}
__global__ void hist_kernel(const int* __restrict__ ed, int* __restrict__ deg, int e) {
    int i = blockIdx.x * blockDim.x + threadIdx.x;
    if (i < e) atomicAdd(&deg[ed[i]], 1);
}
__global__ void scan_kernel(const int* __restrict__ deg, int* __restrict__ off, int n) {
    __shared__ int sm[1024];
    int t = threadIdx.x;
    int chunk = (n + 1023) >> 10;
    int beg = t * chunk;
    int end = min(beg + chunk, n);
    int s = 0;
    for (int i = beg; i < end; i++) s += deg[i];
    sm[t] = s;
    __syncthreads();
    for (int d = 1; d < 1024; d <<= 1) {
        int v = (t >= d) ? sm[t - d] : 0;
        __syncthreads();
        sm[t] += v;
        __syncthreads();
    }
    int pre = (t == 0) ? 0 : sm[t - 1];
    for (int i = beg; i < end; i++) { off[i] = pre; pre += deg[i]; }
    if (t == 1023) off[n] = sm[1023];
}
__global__ void scatter_kernel(const int* __restrict__ es, const int* __restrict__ ed,
                               int* __restrict__ pos, int* __restrict__ csr, int e) {
    int i = blockIdx.x * blockDim.x + threadIdx.x;
    if (i < e) {
        int p = atomicAdd(&pos[ed[i]], 1);
        csr[p] = es[i];
    }
}
__global__ void pre_kernel(const float* __restrict__ a, const float* __restrict__ b,
                           __nv_bfloat16* __restrict__ sb, __nv_bfloat16* __restrict__ c1,
                           __nv_bfloat16* __restrict__ c2, int tot4) {
    int i = blockIdx.x * blockDim.x + threadIdx.x;
    if (i >= tot4) return;
    int row = i >> 5, col = (i & 31) * 4;
    float4 va = reinterpret_cast<const float4*>(a)[i];
    float4 vb = reinterpret_cast<const float4*>(b)[i];
    write4(sb, row, col, va);
    write4(c1, row, col, make_float4(va.x - vb.x, va.y - vb.y, va.z - vb.z, va.w - vb.w));
    write4(c2, row, col, make_float4(va.x * vb.x, va.y * vb.y, va.z * vb.z, va.w * vb.w));
}

// ---------------- aggregation from bf16 hi/lo buffers ----------------
__global__ void agg_kernel(const __nv_bfloat16* __restrict__ hb, const int* __restrict__ off,
                           const int* __restrict__ csr, __nv_bfloat16* __restrict__ meanb,
                           __nv_bfloat16* __restrict__ maxb, int n) {
    int wid = (blockIdx.x * blockDim.x + threadIdx.x) >> 5;
    int lane = threadIdx.x & 31;
    if (wid >= n) return;
    int beg = off[wid], end = off[wid + 1];
    float NI = __int_as_float(0xff800000);
    float4 s = make_float4(0.f, 0.f, 0.f, 0.f);
    float4 m = make_float4(NI, NI, NI, NI);
    const uint2* hp = (const uint2*)hb;
    for (int e = beg; e < end; e++) {
        int src = csr[e];
        uint2 uh = hp[(size_t)src * 64 + lane];
        uint2 ul = hp[(size_t)src * 64 + 32 + lane];
        float2 f0 = __bfloat1622float2(*(__nv_bfloat162*)&uh.x);
        float2 f1 = __bfloat1622float2(*(__nv_bfloat162*)&uh.y);
        float2 g0 = __bfloat1622float2(*(__nv_bfloat162*)&ul.x);
        float2 g1 = __bfloat1622float2(*(__nv_bfloat162*)&ul.y);
        float vx = f0.x + g0.x, vy = f0.y + g0.y, vz = f1.x + g1.x, vw = f1.y + g1.y;
        s.x += vx; s.y += vy; s.z += vz; s.w += vw;
        m.x = fmaxf(m.x, vx); m.y = fmaxf(m.y, vy);
        m.z = fmaxf(m.z, vz); m.w = fmaxf(m.w, vw);
    }
    int deg = end - beg;
    float inv = (deg > 0) ? (1.0f / (float)deg) : 0.f;
    float4 mn = make_float4(s.x * inv, s.y * inv, s.z * inv, s.w * inv);
    float4 mx = (deg > 0) ? m : make_float4(0.f, 0.f, 0.f, 0.f);
    write4(meanb, wid, lane * 4, mn);
    write4(maxb, wid, lane * 4, mx);
}

// ---------------- normalization coefficients ----------------
__global__ void finalize_kernel(const float* __restrict__ stats, const float* __restrict__ g,
                                const float* __restrict__ be, float* __restrict__ coef,
                                int nk, float invN) {
    int i = blockIdx.x * 128 + threadIdx.x;
    if (i < nk * 128) {
        int k = i >> 7, d = i & 127;
        float s = stats[k * 256 + d];
        float q = stats[k * 256 + 128 + d];
        float mu = s * invN;
        float var = fmaxf(q * invN - mu * mu, 0.f);
        float a = rsqrtf(var + 1e-5f) * g[i];
        float c = be[i] - mu * a;
        coef[i] = a;
        coef[nk * 128 + i] = c;
    }
}

// ---------------- host orchestration ----------------
extern "C" void kernel_launch(void* const* d_in, const int* in_sizes, int n_in,
                              void* d_out, int out_size) {
    const float* src_emb = (const float*)d_in[0];
    const float* hr      = (const float*)d_in[1];
    const int*   edge_src = (const int*)d_in[2];
    const int*   edge_dst = (const int*)d_in[3];
    const float* w_zero  = (const float*)d_in[4];
    const float* w_first = (const float*)d_in[5];
    const float* w_mid   = (const float*)d_in[6];
    const float* w_last  = (const float*)d_in[7];
    const float* W_zero  = (const float*)d_in[8];
    const float* b_zero  = (const float*)d_in[9];
    const float* g_zero  = (const float*)d_in[10];
    const float* be_zero = (const float*)d_in[11];
    const float* W_first = (const float*)d_in[12];
    const float* b_first = (const float*)d_in[13];
    const float* g_first = (const float*)d_in[14];
    const float* be_first = (const float*)d_in[15];
    const float* W_mid   = (const float*)d_in[16];
    const float* b_mid   = (const float*)d_in[17];
    const float* g_mid   = (const float*)d_in[18];
    const float* be_mid  = (const float*)d_in[19];
    const float* W_last  = (const float*)d_in[20];
    const float* b_last  = (const float*)d_in[21];
    const float* g_last  = (const float*)d_in[22];
    const float* be_last = (const float*)d_in[23];
    const float* W_cat   = (const float*)d_in[24];
    const float* b_cat   = (const float*)d_in[25];
    const float* g_cat   = (const float*)d_in[26];
    const float* be_cat  = (const float*)d_in[27];

    const int n = in_sizes[0] / D;
    const int e = in_sizes[2];
    float* out = (float*)d_out;

    float *part, *stats, *coef;
    __nv_bfloat16 *sb, *hb0, *hb1, *hb2, *hb3, *mbb, *xbb, *wb;
    int *deg, *off, *pos, *csr;
    cudaGetSymbolAddress((void**)&part, g_part);
    cudaGetSymbolAddress((void**)&sb, g_sb);
    cudaGetSymbolAddress((void**)&hb0, g_hb0);
    cudaGetSymbolAddress((void**)&hb1, g_hb1);
    cudaGetSymbolAddress((void**)&hb2, g_hb2);
    cudaGetSymbolAddress((void**)&hb3, g_hb3);
    cudaGetSymbolAddress((void**)&mbb, g_mbb);
    cudaGetSymbolAddress((void**)&xbb, g_xbb);
    cudaGetSymbolAddress((void**)&wb, g_wb);
    cudaGetSymbolAddress((void**)&stats, g_stats2);
    cudaGetSymbolAddress((void**)&coef, g_coef2);
    cudaGetSymbolAddress((void**)&deg, g_deg);
    cudaGetSymbolAddress((void**)&off, g_off);
    cudaGetSymbolAddress((void**)&pos, g_pos);
    cudaGetSymbolAddress((void**)&csr, g_csr);

    cudaFuncSetAttribute(gemm_p1, cudaFuncAttributeMaxDynamicSharedMemorySize, SMEM_BYTES);
    cudaFuncSetAttribute(gemm_p2, cudaFuncAttributeMaxDynamicSharedMemorySize, SMEM_BYTES);

    const int tot4 = n * 32;
    const int ewb = (tot4 + 255) / 256;
    const int gmb = (n + 127) / 128;
    const float invN = 1.0f / (float)n;

    // weight conversion + stats zero + CSR (independent prep)
    convw_kernel<<<3, 256>>>(W_zero, wb);
    convw_kernel<<<9, 256>>>(W_first, wb + (size_t)3 * 32768);
    convw_kernel<<<6, 256>>>(W_mid, wb + (size_t)12 * 32768);
    convw_kernel<<<6, 256>>>(W_last, wb + (size_t)18 * 32768);
    convw_kernel<<<3, 256>>>(W_cat, wb + (size_t)24 * 32768);
    zerof_kernel<<<27, 256>>>(stats, 6912);
    zeroi_kernel<<<(n + 255) / 256, 256>>>(deg, n);
    hist_kernel<<<(e + 255) / 256, 256>>>(edge_dst, deg, e);
    scan_kernel<<<1, 1024>>>(deg, off, n);
    copyi_kernel<<<(n + 255) / 256, 256>>>(off, pos, n);
    scatter_kernel<<<(e + 255) / 256, 256>>>(edge_src, edge_dst, pos, csr, e);

    auto mixedop = [&](const __nv_bfloat16* x0, const __nv_bfloat16* x1,
                       const __nv_bfloat16* x2, int widx, const float* bb, const float* gg,
                       const float* bbe, const float* wv, int ridx, const float* accin,
                       float* hout, __nv_bfloat16* hbout) {
        float* st = stats + ridx * 768;
        float* cf = coef + ridx * 768;
        dim3 g1(gmb, 3);
        gemm_p1<<<g1, 512, SMEM_BYTES>>>(x0, x1, x2, wb + (size_t)widx * 32768, bb, st, n, 0,
                                         6);
        finalize_kernel<<<3, 128>>>(st, gg, bbe, cf, 3, invN);
        gemm_p2<<<gmb, 512, SMEM_BYTES>>>(x0, x1, x2, wb + (size_t)widx * 32768, bb, cf, wv,
                                          accin, hout, hbout, n, 18, 1, 3);
    };
    auto agg = [&](const __nv_bfloat16* h) {
        agg_kernel<<<ewb, 256>>>(h, off, csr, mbb, xbb, n);
    };

    // zero op
    pre_kernel<<<ewb, 256>>>(src_emb, hr, sb, mbb, xbb, tot4);
    mixedop(sb, mbb, xbb, 0, b_zero, g_zero, be_zero, w_zero, 0, nullptr, nullptr, hb0);

    agg(hb0);
    mixedop(hb0, mbb, xbb, 3, b_first, g_first, be_first, w_first, 1, nullptr, nullptr, hb1);
    mixedop(hb0, mbb, xbb, 6, b_first + 384, g_first + 384, be_first + 384, w_first + 3, 2,
            nullptr, part, nullptr);
    agg(hb1);
    mixedop(hb1, mbb, xbb, 9, b_first + 768, g_first + 768, be_first + 768, w_first + 6, 3,
            part, nullptr, hb2);
    mixedop(hb1, mbb, xbb, 12, b_mid, g_mid, be_mid, w_mid, 4, nullptr, nullptr, hb3);
    agg(hb2);
    mixedop(hb2, mbb, xbb, 15, b_mid + 384, g_mid + 384, be_mid + 384, w_mid + 3, 5, nullptr,
            nullptr, hb0);
    agg(hb3);
    mixedop(hb3, mbb, xbb, 18, b_last, g_last, be_last, w_last, 6, nullptr, part, nullptr);
    agg(hb0);
    mixedop(hb0, mbb, xbb, 21, b_last + 384, g_last + 384, be_last + 384, w_last + 3, 7,
            part, nullptr, hb1);

    // concat GEMM + batchnorm + relu -> out
    {
        float* st = stats + 8 * 768;
        float* cf = coef + 8 * 768;
        gemm_p1<<<gmb, 512, SMEM_BYTES>>>(hb3, hb0, hb1, wb + (size_t)24 * 32768, b_cat, st,
                                          n, 1, 18);
        finalize_kernel<<<1, 128>>>(st, g_cat, be_cat, cf, 1, invN);
        gemm_p2<<<gmb, 512, SMEM_BYTES>>>(hb3, hb0, hb1, wb + (size_t)24 * 32768, b_cat, cf,
                                          nullptr, nullptr, out, nullptr, n, 18, 0, 1);
    }
}

// round 7
// speedup vs baseline: 2.2328x; 2.2328x over previous
#include <cuda_runtime.h>
#include <cuda_bf16.h>
#include <cstdint>

#define D 128
#define NMAX 100000
#define EMAX 600000

// ---------------- scratch (static __device__, no allocations) ----------------
__device__ float g_h0[NMAX * D];
__device__ float g_h1[NMAX * D];
__device__ float g_h2[NMAX * D];
__device__ float g_h3[NMAX * D];
__device__ float g_y[3L * NMAX * D];  // gemm outputs
// bf16 hi/lo activation buffers: rows of 256 bf16 = [hi(128) | lo(128)]
__device__ __nv_bfloat16 g_sb[NMAX * 256];   // src_emb
__device__ __nv_bfloat16 g_hb0[NMAX * 256];
__device__ __nv_bfloat16 g_hb1[NMAX * 256];
__device__ __nv_bfloat16 g_hb2[NMAX * 256];
__device__ __nv_bfloat16 g_hb3[NMAX * 256];
__device__ __nv_bfloat16 g_mbb[NMAX * 256];  // mean agg / pre-cand1
__device__ __nv_bfloat16 g_xbb[NMAX * 256];  // max agg  / pre-cand2
__device__ __nv_bfloat16 g_wb[27 * 32768];   // 27 transposed weight mats [f][hi d|lo d]
__device__ int   g_deg[NMAX];
__device__ int   g_off[NMAX + 1];
__device__ int   g_pos[NMAX];
__device__ int   g_csr[EMAX];
__device__ float g_stats[768];
__device__ float g_coef[768];

// ================= helpers =================
__device__ __forceinline__ uint32_t smem_u32(const void* p) {
    uint32_t a;
    asm("{ .reg .u64 t; cvta.to.shared.u64 t, %1; cvt.u32.u64 %0, t; }" : "=r"(a) : "l"(p));
    return a;
}
__device__ __forceinline__ void ldsm4(uint32_t addr, uint32_t* r) {
    asm volatile("ldmatrix.sync.aligned.m8n8.x4.shared.b16 {%0,%1,%2,%3}, [%4];"
                 : "=r"(r[0]), "=r"(r[1]), "=r"(r[2]), "=r"(r[3]) : "r"(addr));
}
__device__ __forceinline__ void mma16816(float* c, const uint32_t* a, uint32_t b0,
                                         uint32_t b1) {
    asm volatile(
        "mma.sync.aligned.m16n8k16.row.col.f32.bf16.bf16.f32 "
        "{%0,%1,%2,%3}, {%4,%5,%6,%7}, {%8,%9}, {%0,%1,%2,%3};"
        : "+f"(c[0]), "+f"(c[1]), "+f"(c[2]), "+f"(c[3])
        : "r"(a[0]), "r"(a[1]), "r"(a[2]), "r"(a[3]), "r"(b0), "r"(b1));
}
__device__ __forceinline__ void cpa16(uint32_t dst, const void* src, uint32_t sz) {
    asm volatile("cp.async.cg.shared.global [%0], [%1], 16, %2;" ::"r"(dst), "l"(src),
                 "r"(sz));
}
#define CPCOMMIT() asm volatile("cp.async.commit_group;" ::: "memory")
#define CPWAIT0() asm volatile("cp.async.wait_group 0;" ::: "memory")
__device__ __forceinline__ uint32_t b2u(__nv_bfloat162 v) {
    return *reinterpret_cast<uint32_t*>(&v);
}
// split 2 floats -> packed hi bf16x2 + lo bf16x2
__device__ __forceinline__ void split2(float2 p, uint32_t& hi, uint32_t& lo) {
    __nv_bfloat162 h = __float22bfloat162_rn(p);
    float2 hb = __bfloat1622float2(h);
    float2 r = make_float2(p.x - hb.x, p.y - hb.y);
    __nv_bfloat162 l = __float22bfloat162_rn(r);
    hi = b2u(h);
    lo = b2u(l);
}
__device__ __forceinline__ void write4(__nv_bfloat16* buf, int row, int col, float4 v) {
    uint32_t h0, l0, h1, l1;
    split2(make_float2(v.x, v.y), h0, l0);
    split2(make_float2(v.z, v.w), h1, l1);
    *reinterpret_cast<uint2*>(buf + (size_t)row * 256 + col) = make_uint2(h0, h1);
    *reinterpret_cast<uint2*>(buf + (size_t)row * 256 + 128 + col) = make_uint2(l0, l1);
}

// smem layout: A[64 rows][512B + 16B pad], B[128 rows][512B + 16B pad], bias/csum/csq
#define LDKB 528
#define ASZ (64 * LDKB)          // 33792
#define SM_B_OFF ASZ
#define SM_BIAS (ASZ + 128 * LDKB)  // 101376
#define SM_CSUM (SM_BIAS + 512)
#define SM_CSQ (SM_BIAS + 1024)
#define SMEM_BYTES (SM_BIAS + 1536)  // 102912 -> 2 CTAs/SM

// cp.async A tile: 64 rows x 512B (zfill beyond n)
__device__ __forceinline__ void load_Abf(uint32_t sA, const __nv_bfloat16* __restrict__ xb,
                                         int row0, int n, int t) {
#pragma unroll
    for (int j = 0; j < 8; j++) {
        int u = j * 256 + t;  // 0..2047 uint4 slots
        int row = u >> 5, c = u & 31;
        int gr = row0 + row;
        uint32_t sz = gr < n ? 16u : 0u;
        int gs = gr < n ? gr : 0;
        cpa16(sA + row * LDKB + c * 16, (const char*)xb + (size_t)gs * 512 + c * 16, sz);
    }
}
// cp.async B tile: 128 rows x 512B
__device__ __forceinline__ void load_Bbf(uint32_t sB, const __nv_bfloat16* __restrict__ wm,
                                         int t) {
#pragma unroll
    for (int j = 0; j < 16; j++) {
        int u = j * 256 + t;  // 0..4095
        int row = u >> 5, c = u & 31;
        cpa16(sB + row * LDKB + c * 16, (const char*)wm + (size_t)row * 512 + c * 16, 16u);
    }
}

// mainloop: 8 k-steps, 3-term split (AhBh + AlBh + AhBl); warp grid 2(m) x 4(n)
__device__ __forceinline__ void mma_pass(uint32_t sA, uint32_t sB, float acc[2][4][4],
                                         int wm, int wn, int lane) {
    uint32_t a_base = sA + (uint32_t)(wm * 32 + (lane & 15)) * LDKB + (uint32_t)(lane >> 4) * 16;
    uint32_t b_base = sB + (uint32_t)(wn * 32 + (lane & 15)) * LDKB + (uint32_t)(lane >> 4) * 16;
#pragma unroll
    for (int ks = 0; ks < 8; ks++) {
        uint32_t kb = (uint32_t)ks * 32;
        uint32_t ah[2][4], al[2][4], bh[2][4], bl[2][4];
        ldsm4(a_base + kb, ah[0]);
        ldsm4(a_base + 16 * LDKB + kb, ah[1]);
        ldsm4(a_base + 256 + kb, al[0]);
        ldsm4(a_base + 16 * LDKB + 256 + kb, al[1]);
        ldsm4(b_base + kb, bh[0]);
        ldsm4(b_base + 16 * LDKB + kb, bh[1]);
        ldsm4(b_base + 256 + kb, bl[0]);
        ldsm4(b_base + 16 * LDKB + 256 + kb, bl[1]);
#pragma unroll
        for (int mt = 0; mt < 2; mt++)
#pragma unroll
            for (int nt = 0; nt < 4; nt++) {
                int nt2 = nt >> 1, p = nt & 1;
                mma16816(acc[mt][nt], ah[mt], bh[nt2][p], bh[nt2][p + 2]);
                mma16816(acc[mt][nt], al[mt], bh[nt2][p], bh[nt2][p + 2]);
                mma16816(acc[mt][nt], ah[mt], bl[nt2][p], bl[nt2][p + 2]);
            }
    }
}

// epilogue: bias, store y, column sum/sumsq via warp shfl + smem atomics
__device__ __forceinline__ void epilogue(float acc[2][4][4], float* __restrict__ y,
                                         const float* sbias, float* csum, float* csq,
                                         int row0, int n, int wm, int wn, int lane) {
    float ps[4][2], pq[4][2];
#pragma unroll
    for (int nt = 0; nt < 4; nt++) {
        ps[nt][0] = 0.f; ps[nt][1] = 0.f; pq[nt][0] = 0.f; pq[nt][1] = 0.f;
    }
    int mrow = row0 + wm * 32 + (lane >> 2);
#pragma unroll
    for (int mt = 0; mt < 2; mt++) {
#pragma unroll
        for (int h = 0; h < 2; h++) {
            int r = mrow + mt * 16 + h * 8;
            bool ok = r < n;
            float* yr = y + (size_t)r * D;
#pragma unroll
            for (int nt = 0; nt < 4; nt++) {
                int col = wn * 32 + nt * 8 + (lane & 3) * 2;
                float c0 = acc[mt][nt][h * 2 + 0] + sbias[col];
                float c1 = acc[mt][nt][h * 2 + 1] + sbias[col + 1];
                if (ok) {
                    *(float2*)(yr + col) = make_float2(c0, c1);
                    ps[nt][0] += c0; ps[nt][1] += c1;
                    pq[nt][0] += c0 * c0; pq[nt][1] += c1 * c1;
                }
            }
        }
    }
#pragma unroll
    for (int off = 16; off >= 4; off >>= 1) {
#pragma unroll
        for (int nt = 0; nt < 4; nt++) {
            ps[nt][0] += __shfl_xor_sync(0xffffffffu, ps[nt][0], off);
            ps[nt][1] += __shfl_xor_sync(0xffffffffu, ps[nt][1], off);
            pq[nt][0] += __shfl_xor_sync(0xffffffffu, pq[nt][0], off);
            pq[nt][1] += __shfl_xor_sync(0xffffffffu, pq[nt][1], off);
        }
    }
    if ((lane >> 2) == 0) {
#pragma unroll
        for (int nt = 0; nt < 4; nt++) {
            int col = wn * 32 + nt * 8 + (lane & 3) * 2;
            atomicAdd(&csum[col], ps[nt][0]);
            atomicAdd(&csum[col + 1], ps[nt][1]);
            atomicAdd(&csq[col], pq[nt][0]);
            atomicAdd(&csq[col + 1], pq[nt][1]);
        }
    }
}

// ---------------- weight pre-conversion: transpose + bf16 hi/lo split ----------------
__global__ void convw_kernel(const float* __restrict__ W, __nv_bfloat16* __restrict__ dst) {
    int bm = blockIdx.x;
    const float* Wk = W + (size_t)bm * 16384;
    __nv_bfloat16* ob = dst + (size_t)bm * 32768;
    int t = threadIdx.x;
    int f = t & 127;
    int d0 = (t >> 7) * 64;
#pragma unroll 4
    for (int jd = 0; jd < 64; jd += 4) {
        int d = d0 + jd;
        float w0 = Wk[(size_t)(d + 0) * D + f];
        float w1 = Wk[(size_t)(d + 1) * D + f];
        float w2 = Wk[(size_t)(d + 2) * D + f];
        float w3 = Wk[(size_t)(d + 3) * D + f];
        uint32_t h0, l0, h1, l1;
        split2(make_float2(w0, w1), h0, l0);
        split2(make_float2(w2, w3), h1, l1);
        *reinterpret_cast<uint2*>(ob + (size_t)f * 256 + d) = make_uint2(h0, h1);
        *reinterpret_cast<uint2*>(ob + (size_t)f * 256 + 128 + d) = make_uint2(l0, l1);
    }
}

// ---------------- GEMM (3 parallel N x 128 x 128), M=64 tiles ----------------
__global__ void __launch_bounds__(256) gemm3_tc_kernel(
    const __nv_bfloat16* __restrict__ x0, const __nv_bfloat16* __restrict__ x1,
    const __nv_bfloat16* __restrict__ x2, const __nv_bfloat16* __restrict__ wbase,
    const float* __restrict__ b, float* __restrict__ y, float* __restrict__ stats, int n) {
    extern __shared__ char sc[];
    uint32_t sbase = smem_u32(sc);
    float* sbias = (float*)(sc + SM_BIAS);
    float* csum = (float*)(sc + SM_CSUM);
    float* csq = (float*)(sc + SM_CSQ);

    const int t = threadIdx.x;
    const int wid = t >> 5, lane = t & 31;
    const int wm = wid & 1, wn = wid >> 1;
    const int kidx = blockIdx.y;
    const __nv_bfloat16* __restrict__ x = kidx == 0 ? x0 : (kidx == 1 ? x1 : x2);
    const int row0 = blockIdx.x * 64;

    load_Abf(sbase, x, row0, n, t);
    load_Bbf(sbase + SM_B_OFF, wbase + (size_t)kidx * 32768, t);
    CPCOMMIT();
    if (t < 128) {
        sbias[t] = b[kidx * D + t];
        csum[t] = 0.f;
        csq[t] = 0.f;
    }
    CPWAIT0();
    __syncthreads();

    float acc[2][4][4];
#pragma unroll
    for (int i = 0; i < 2; i++)
#pragma unroll
        for (int j = 0; j < 4; j++)
#pragma unroll
            for (int q = 0; q < 4; q++) acc[i][j][q] = 0.f;

    mma_pass(sbase, sbase + SM_B_OFF, acc, wm, wn, lane);

    epilogue(acc, y + (size_t)kidx * n * D, sbias, csum, csq, row0, n, wm, wn, lane);
    __syncthreads();
    if (t < 128) {
        atomicAdd(&stats[kidx * 256 + t], csum[t]);
        atomicAdd(&stats[kidx * 256 + 128 + t], csq[t]);
    }
}

// ---------------- concat GEMM (K = 3x128 from three sources), M=64 tiles ------------
__global__ void __launch_bounds__(256) gemmcat_tc_kernel(
    const __nv_bfloat16* __restrict__ x0, const __nv_bfloat16* __restrict__ x1,
    const __nv_bfloat16* __restrict__ x2, const __nv_bfloat16* __restrict__ wbase,
    const float* __restrict__ bc, float* __restrict__ y, float* __restrict__ stats, int n) {
    extern __shared__ char sc[];
    uint32_t sbase = smem_u32(sc);
    float* sbias = (float*)(sc + SM_BIAS);
    float* csum = (float*)(sc + SM_CSUM);
    float* csq = (float*)(sc + SM_CSQ);

    const int t = threadIdx.x;
    const int wid = t >> 5, lane = t & 31;
    const int wm = wid & 1, wn = wid >> 1;
    const int row0 = blockIdx.x * 64;

    if (t < 128) {
        sbias[t] = bc[t];
        csum[t] = 0.f;
        csq[t] = 0.f;
    }

    float acc[2][4][4];
#pragma unroll
    for (int i = 0; i < 2; i++)
#pragma unroll
        for (int j = 0; j < 4; j++)
#pragma unroll
            for (int q = 0; q < 4; q++) acc[i][j][q] = 0.f;

    for (int c = 0; c < 3; c++) {
        if (c) __syncthreads();
        const __nv_bfloat16* __restrict__ x = c == 0 ? x0 : (c == 1 ? x1 : x2);
        load_Abf(sbase, x, row0, n, t);
        load_Bbf(sbase + SM_B_OFF, wbase + (size_t)c * 32768, t);
        CPCOMMIT();
        CPWAIT0();
        __syncthreads();
        mma_pass(sbase, sbase + SM_B_OFF, acc, wm, wn, lane);
    }

    epilogue(acc, y, sbias, csum, csq, row0, n, wm, wn, lane);
    __syncthreads();
    if (t < 128) {
        atomicAdd(&stats[t], csum[t]);
        atomicAdd(&stats[128 + t], csq[t]);
    }
}

// ---------------- small utility kernels ----------------
__global__ void zerof_kernel(float* p, int nel) {
    int i = blockIdx.x * blockDim.x + threadIdx.x;
    if (i < nel) p[i] = 0.f;
}
__global__ void zeroi_kernel(int* p, int nel) {
    int i = blockIdx.x * blockDim.x + threadIdx.x;
    if (i < nel) p[i] = 0;
}
__global__ void copyi_kernel(const int* __restrict__ a, int* __restrict__ b, int nel) {
    int i = blockIdx.x * blockDim.x + threadIdx.x;
    if (i < nel) b[i] = a[i];
}
__global__ void hist_kernel(const int* __restrict__ ed, int* __restrict__ deg, int e) {
    int i = blockIdx.x * blockDim.x + threadIdx.x;
    if (i < e) atomicAdd(&deg[ed[i]], 1);
}
__global__ void scan_kernel(const int* __restrict__ deg, int* __restrict__ off, int n) {
    __shared__ int sm[1024];
    int t = threadIdx.x;
    int chunk = (n + 1023) >> 10;
    int beg = t * chunk;
    int end = min(beg + chunk, n);
    int s = 0;
    for (int i = beg; i < end; i++) s += deg[i];
    sm[t] = s;
    __syncthreads();
    for (int d = 1; d < 1024; d <<= 1) {
        int v = (t >= d) ? sm[t - d] : 0;
        __syncthreads();
        sm[t] += v;
        __syncthreads();
    }
    int pre = (t == 0) ? 0 : sm[t - 1];
    for (int i = beg; i < end; i++) { off[i] = pre; pre += deg[i]; }
    if (t == 1023) off[n] = sm[1023];
}
__global__ void scatter_kernel(const int* __restrict__ es, const int* __restrict__ ed,
                               int* __restrict__ pos, int* __restrict__ csr, int e) {
    int i = blockIdx.x * blockDim.x + threadIdx.x;
    if (i < e) {
        int p = atomicAdd(&pos[ed[i]], 1);
        csr[p] = es[i];
    }
}
// pre: cand0 = src_emb, cand1 = src - hr, cand2 = src * hr -> bf16 hi/lo buffers
__global__ void pre_kernel(const float* __restrict__ a, const float* __restrict__ b,
                           __nv_bfloat16* __restrict__ sb, __nv_bfloat16* __restrict__ c1,
                           __nv_bfloat16* __restrict__ c2, int tot4) {
    int i = blockIdx.x * blockDim.x + threadIdx.x;
    if (i >= tot4) return;
    int row = i >> 5, col = (i & 31) * 4;
    float4 va = reinterpret_cast<const float4*>(a)[i];
    float4 vb = reinterpret_cast<const float4*>(b)[i];
    write4(sb, row, col, va);
    write4(c1, row, col, make_float4(va.x - vb.x, va.y - vb.y, va.z - vb.z, va.w - vb.w));
    write4(c2, row, col, make_float4(va.x * vb.x, va.y * vb.y, va.z * vb.z, va.w * vb.w));
}

// ---------------- aggregation: warp per node, CSR, bf16 hi/lo outputs ----------------
__global__ void agg_kernel(const float* __restrict__ h, const int* __restrict__ off,
                           const int* __restrict__ csr, __nv_bfloat16* __restrict__ meanb,
                           __nv_bfloat16* __restrict__ maxb, int n) {
    int wid = (blockIdx.x * blockDim.x + threadIdx.x) >> 5;
    int lane = threadIdx.x & 31;
    if (wid >= n) return;
    int beg = off[wid], end = off[wid + 1];
    float NI = __int_as_float(0xff800000);
    float4 s = make_float4(0.f, 0.f, 0.f, 0.f);
    float4 m = make_float4(NI, NI, NI, NI);
    for (int e = beg; e < end; e++) {
        int src = csr[e];
        float4 v = *reinterpret_cast<const float4*>(h + (size_t)src * D + lane * 4);
        s.x += v.x; s.y += v.y; s.z += v.z; s.w += v.w;
        m.x = fmaxf(m.x, v.x); m.y = fmaxf(m.y, v.y);
        m.z = fmaxf(m.z, v.z); m.w = fmaxf(m.w, v.w);
    }
    int deg = end - beg;
    float inv = (deg > 0) ? (1.0f / (float)deg) : 0.f;
    float4 mn = make_float4(s.x * inv, s.y * inv, s.z * inv, s.w * inv);
    float4 mx = (deg > 0) ? m : make_float4(0.f, 0.f, 0.f, 0.f);
    write4(meanb, wid, lane * 4, mn);
    write4(maxb, wid, lane * 4, mx);
}

// ---------------- normalization coefficient computation ----------------
__global__ void finalize_kernel(const float* __restrict__ stats, const float* __restrict__ g,
                                const float* __restrict__ be, float* __restrict__ coef,
                                int nk, float invN) {
    int i = blockIdx.x * 128 + threadIdx.x;
    if (i < nk * 128) {
        int k = i >> 7, d = i & 127;
        float s = stats[k * 256 + d];
        float q = stats[k * 256 + 128 + d];
        float mu = s * invN;
        float var = fmaxf(q * invN - mu * mu, 0.f);
        float a = rsqrtf(var + 1e-5f) * g[i];
        float c = be[i] - mu * a;
        coef[i] = a;
        coef[nk * 128 + i] = c;
    }
}

// ---------------- normalize + relu + weighted combine (fp32 h + bf16 hi/lo h) ----------
__global__ void combine3_kernel(const float* __restrict__ y, int n,
                                const float* __restrict__ coef, const float* __restrict__ wv,
                                float* __restrict__ out, __nv_bfloat16* __restrict__ hb,
                                int accf) {
    __shared__ float sA[384], sC[384], sw[3];
    int t = threadIdx.x;
    for (int i = t; i < 384; i += blockDim.x) { sA[i] = coef[i]; sC[i] = coef[384 + i]; }
    if (t < 3) sw[t] = wv[t];
    __syncthreads();
    int tot4 = n * 32;
    int i = blockIdx.x * blockDim.x + t;
    if (i >= tot4) return;
    int col = (i * 4) & 127;
    int row = i >> 5;
    size_t stride = (size_t)n * 32;
    const float4* y4 = reinterpret_cast<const float4*>(y);
    float4 a0 = *reinterpret_cast<float4*>(&sA[col]);
    float4 c0 = *reinterpret_cast<float4*>(&sC[col]);
    float4 a1 = *reinterpret_cast<float4*>(&sA[128 + col]);
    float4 c1 = *reinterpret_cast<float4*>(&sC[128 + col]);
    float4 a2 = *reinterpret_cast<float4*>(&sA[256 + col]);
    float4 c2 = *reinterpret_cast<float4*>(&sC[256 + col]);
    float4 y0 = y4[i], y1 = y4[i + stride], y2 = y4[i + 2 * stride];
    float w0 = sw[0], w1 = sw[1], w2 = sw[2];
    float4 r;
    r.x = w0 * fmaxf(fmaf(y0.x, a0.x, c0.x), 0.f) + w1 * fmaxf(fmaf(y1.x, a1.x, c1.x), 0.f) +
          w2 * fmaxf(fmaf(y2.x, a2.x, c2.x), 0.f);
    r.y = w0 * fmaxf(fmaf(y0.y, a0.y, c0.y), 0.f) + w1 * fmaxf(fmaf(y1.y, a1.y, c1.y), 0.f) +
          w2 * fmaxf(fmaf(y2.y, a2.y, c2.y), 0.f);
    r.z = w0 * fmaxf(fmaf(y0.z, a0.z, c0.z), 0.f) + w1 * fmaxf(fmaf(y1.z, a1.z, c1.z), 0.f) +
          w2 * fmaxf(fmaf(y2.z, a2.z, c2.z), 0.f);
    r.w = w0 * fmaxf(fmaf(y0.w, a0.w, c0.w), 0.f) + w1 * fmaxf(fmaf(y1.w, a1.w, c1.w), 0.f) +
          w2 * fmaxf(fmaf(y2.w, a2.w, c2.w), 0.f);
    float4* o4 = reinterpret_cast<float4*>(out);
    if (accf) {
        float4 p = o4[i];
        r.x += p.x; r.y += p.y; r.z += p.z; r.w += p.w;
    }
    o4[i] = r;
    write4(hb, row, col, r);
}

__global__ void combinecat_kernel(const float* __restrict__ y, int n,
                                  const float* __restrict__ coef, float* __restrict__ out) {
    __shared__ float sA[128], sC[128];
    int t = threadIdx.x;
    if (t < 128) { sA[t] = coef[t]; sC[t] = coef[128 + t]; }
    __syncthreads();
    int tot4 = n * 32;
    int i = blockIdx.x * blockDim.x + t;
    if (i >= tot4) return;
    int col = (i * 4) & 127;
    float4 a = *reinterpret_cast<float4*>(&sA[col]);
    float4 c = *reinterpret_cast<float4*>(&sC[col]);
    float4 v = reinterpret_cast<const float4*>(y)[i];
    float4 r;
    r.x = fmaxf(fmaf(v.x, a.x, c.x), 0.f);
    r.y = fmaxf(fmaf(v.y, a.y, c.y), 0.f);
    r.z = fmaxf(fmaf(v.z, a.z, c.z), 0.f);
    r.w = fmaxf(fmaf(v.w, a.w, c.w), 0.f);
    reinterpret_cast<float4*>(out)[i] = r;
}

// ---------------- host orchestration ----------------
extern "C" void kernel_launch(void* const* d_in, const int* in_sizes, int n_in,
                              void* d_out, int out_size) {
    const float* src_emb = (const float*)d_in[0];
    const float* hr      = (const float*)d_in[1];
    const int*   edge_src = (const int*)d_in[2];
    const int*   edge_dst = (const int*)d_in[3];
    const float* w_zero  = (const float*)d_in[4];
    const float* w_first = (const float*)d_in[5];
    const float* w_mid   = (const float*)d_in[6];
    const float* w_last  = (const float*)d_in[7];
    const float* W_zero  = (const float*)d_in[8];
    const float* b_zero  = (const float*)d_in[9];
    const float* g_zero  = (const float*)d_in[10];
    const float* be_zero = (const float*)d_in[11];
    const float* W_first = (const float*)d_in[12];
    const float* b_first = (const float*)d_in[13];
    const float* g_first = (const float*)d_in[14];
    const float* be_first = (const float*)d_in[15];
    const float* W_mid   = (const float*)d_in[16];
    const float* b_mid   = (const float*)d_in[17];
    const float* g_mid   = (const float*)d_in[18];
    const float* be_mid  = (const float*)d_in[19];
    const float* W_last  = (const float*)d_in[20];
    const float* b_last  = (const float*)d_in[21];
    const float* g_last  = (const float*)d_in[22];
    const float* be_last = (const float*)d_in[23];
    const float* W_cat   = (const float*)d_in[24];
    const float* b_cat   = (const float*)d_in[25];
    const float* g_cat   = (const float*)d_in[26];
    const float* be_cat  = (const float*)d_in[27];

    const int n = in_sizes[0] / D;
    const int e = in_sizes[2];
    float* out = (float*)d_out;

    float *h0, *h1, *h2, *h3, *yb, *stats, *coef;
    __nv_bfloat16 *sb, *hb0, *hb1, *hb2, *hb3, *mbb, *xbb, *wb;
    int *deg, *off, *pos, *csr;
    cudaGetSymbolAddress((void**)&h0, g_h0);
    cudaGetSymbolAddress((void**)&h1, g_h1);
    cudaGetSymbolAddress((void**)&h2, g_h2);
    cudaGetSymbolAddress((void**)&h3, g_h3);
    cudaGetSymbolAddress((void**)&yb, g_y);
    cudaGetSymbolAddress((void**)&sb, g_sb);
    cudaGetSymbolAddress((void**)&hb0, g_hb0);
    cudaGetSymbolAddress((void**)&hb1, g_hb1);
    cudaGetSymbolAddress((void**)&hb2, g_hb2);
    cudaGetSymbolAddress((void**)&hb3, g_hb3);
    cudaGetSymbolAddress((void**)&mbb, g_mbb);
    cudaGetSymbolAddress((void**)&xbb, g_xbb);
    cudaGetSymbolAddress((void**)&wb, g_wb);
    cudaGetSymbolAddress((void**)&stats, g_stats);
    cudaGetSymbolAddress((void**)&coef, g_coef);
    cudaGetSymbolAddress((void**)&deg, g_deg);
    cudaGetSymbolAddress((void**)&off, g_off);
    cudaGetSymbolAddress((void**)&pos, g_pos);
    cudaGetSymbolAddress((void**)&csr, g_csr);

    cudaFuncSetAttribute(gemm3_tc_kernel, cudaFuncAttributeMaxDynamicSharedMemorySize,
                         SMEM_BYTES);
    cudaFuncSetAttribute(gemmcat_tc_kernel, cudaFuncAttributeMaxDynamicSharedMemorySize,
                         SMEM_BYTES);

    const int tot4 = n * 32;
    const int ewb = (tot4 + 255) / 256;
    const int gmb = (n + 63) / 64;
    const float invN = 1.0f / (float)n;

    // --- weight pre-conversion (27 matrices) ---
    convw_kernel<<<3, 256>>>(W_zero, wb);
    convw_kernel<<<9, 256>>>(W_first, wb + (size_t)3 * 32768);
    convw_kernel<<<6, 256>>>(W_mid, wb + (size_t)12 * 32768);
    convw_kernel<<<6, 256>>>(W_last, wb + (size_t)18 * 32768);
    convw_kernel<<<3, 256>>>(W_cat, wb + (size_t)24 * 32768);

    // --- CSR build ---
    zeroi_kernel<<<(n + 255) / 256, 256>>>(deg, n);
    hist_kernel<<<(e + 255) / 256, 256>>>(edge_dst, deg, e);
    scan_kernel<<<1, 1024>>>(deg, off, n);
    copyi_kernel<<<(n + 255) / 256, 256>>>(off, pos, n);
    scatter_kernel<<<(e + 255) / 256, 256>>>(edge_src, edge_dst, pos, csr, e);

    auto mixed = [&](const __nv_bfloat16* x0, const __nv_bfloat16* x1,
                     const __nv_bfloat16* x2, int wbidx, const float* bb, const float* gg,
                     const float* bbe, const float* wv, float* outp, __nv_bfloat16* hbout,
                     int accf) {
        zerof_kernel<<<3, 256>>>(stats, 768);
        dim3 grid(gmb, 3);
        gemm3_tc_kernel<<<grid, 256, SMEM_BYTES>>>(x0, x1, x2, wb + (size_t)wbidx * 32768,
                                                   bb, yb, stats, n);
        finalize_kernel<<<3, 128>>>(stats, gg, bbe, coef, 3, invN);
        combine3_kernel<<<ewb, 256>>>(yb, n, coef, wv, outp, hbout, accf);
    };
    auto agg = [&](const float* h) {
        agg_kernel<<<ewb, 256>>>(h, off, csr, mbb, xbb, n);
    };

    // --- zero op ---
    pre_kernel<<<ewb, 256>>>(src_emb, hr, sb, mbb, xbb, tot4);
    mixed(sb, mbb, xbb, 0, b_zero, g_zero, be_zero, w_zero, h0, hb0, 0);

    // --- s0 and s1 term 1 share agg(h_in) ---
    agg(h0);
    mixed(hb0, mbb, xbb, 3, b_first, g_first, be_first, w_first, h1, hb1, 0);
    mixed(hb0, mbb, xbb, 6, b_first + 384, g_first + 384, be_first + 384, w_first + 3, h2,
          hb2, 0);
    agg(h1);
    mixed(hb1, mbb, xbb, 9, b_first + 768, g_first + 768, be_first + 768, w_first + 6, h2,
          hb2, 1);
    mixed(hb1, mbb, xbb, 12, b_mid, g_mid, be_mid, w_mid, h3, hb3, 0);
    agg(h2);
    mixed(hb2, mbb, xbb, 15, b_mid + 384, g_mid + 384, be_mid + 384, w_mid + 3, h0, hb0, 0);
    agg(h3);
    mixed(hb3, mbb, xbb, 18, b_last, g_last, be_last, w_last, h1, hb1, 0);
    agg(h0);
    mixed(hb0, mbb, xbb, 21, b_last + 384, g_last + 384, be_last + 384, w_last + 3, h1, hb1,
          1);

    // --- concat GEMM + batchnorm + relu -> out ---
    zerof_kernel<<<2, 256>>>(stats, 512);
    gemmcat_tc_kernel<<<gmb, 256, SMEM_BYTES>>>(hb3, hb0, hb1, wb + (size_t)24 * 32768,
                                                b_cat, yb, stats, n);
    finalize_kernel<<<1, 128>>>(stats, g_cat, be_cat, coef, 1, invN);
    combinecat_kernel<<<ewb, 256>>>(yb, n, coef, out);
}

// round 8
// speedup vs baseline: 2.3028x; 1.0314x over previous
#include <cuda_runtime.h>
#include <cuda_bf16.h>
#include <cstdint>

#define D 128
#define NMAX 100000
#define EMAX 600000

// ---------------- scratch (static __device__, no allocations) ----------------
__device__ float g_part[NMAX * D];            // fp32 partial for accumulation chains
__device__ float g_y[3L * NMAX * D];          // gemm outputs (fp32)
// bf16 hi/lo activation buffers: rows of 256 bf16 = [hi(128) | lo(128)]
__device__ __nv_bfloat16 g_sb[NMAX * 256];    // src_emb
__device__ __nv_bfloat16 g_hb0[NMAX * 256];
__device__ __nv_bfloat16 g_hb1[NMAX * 256];
__device__ __nv_bfloat16 g_hb2[NMAX * 256];
__device__ __nv_bfloat16 g_hb3[NMAX * 256];
__device__ __nv_bfloat16 g_mbb[NMAX * 256];   // mean agg / pre-cand1
__device__ __nv_bfloat16 g_xbb[NMAX * 256];   // max agg  / pre-cand2
__device__ __nv_bfloat16 g_wb[27 * 32768];    // 27 transposed weight mats [f][hi d|lo d]
__device__ int   g_deg[NMAX];
__device__ int   g_off[NMAX + 1];
__device__ int   g_pos[NMAX];
__device__ int   g_csr[EMAX];
__device__ float g_stats[768];
__device__ float g_coef[768];

// ================= helpers =================
__device__ __forceinline__ uint32_t smem_u32(const void* p) {
    uint32_t a;
    asm("{ .reg .u64 t; cvta.to.shared.u64 t, %1; cvt.u32.u64 %0, t; }" : "=r"(a) : "l"(p));
    return a;
}
__device__ __forceinline__ void ldsm4(uint32_t addr, uint32_t* r) {
    asm volatile("ldmatrix.sync.aligned.m8n8.x4.shared.b16 {%0,%1,%2,%3}, [%4];"
                 : "=r"(r[0]), "=r"(r[1]), "=r"(r[2]), "=r"(r[3]) : "r"(addr));
}
__device__ __forceinline__ void mma16816(float* c, const uint32_t* a, uint32_t b0,
                                         uint32_t b1) {
    asm volatile(
        "mma.sync.aligned.m16n8k16.row.col.f32.bf16.bf16.f32 "
        "{%0,%1,%2,%3}, {%4,%5,%6,%7}, {%8,%9}, {%0,%1,%2,%3};"
        : "+f"(c[0]), "+f"(c[1]), "+f"(c[2]), "+f"(c[3])
        : "r"(a[0]), "r"(a[1]), "r"(a[2]), "r"(a[3]), "r"(b0), "r"(b1));
}
__device__ __forceinline__ void cpa16(uint32_t dst, const void* src, uint32_t sz) {
    asm volatile("cp.async.cg.shared.global [%0], [%1], 16, %2;" ::"r"(dst), "l"(src),
                 "r"(sz));
}
#define CPCOMMIT() asm volatile("cp.async.commit_group;" ::: "memory")
#define CPWAIT0() asm volatile("cp.async.wait_group 0;" ::: "memory")
__device__ __forceinline__ uint32_t b2u(__nv_bfloat162 v) {
    return *reinterpret_cast<uint32_t*>(&v);
}
// split 2 floats -> packed hi bf16x2 + lo bf16x2
__device__ __forceinline__ void split2(float2 p, uint32_t& hi, uint32_t& lo) {
    __nv_bfloat162 h = __float22bfloat162_rn(p);
    float2 hb = __bfloat1622float2(h);
    float2 r = make_float2(p.x - hb.x, p.y - hb.y);
    __nv_bfloat162 l = __float22bfloat162_rn(r);
    hi = b2u(h);
    lo = b2u(l);
}
__device__ __forceinline__ void write4(__nv_bfloat16* buf, int row, int col, float4 v) {
    uint32_t h0, l0, h1, l1;
    split2(make_float2(v.x, v.y), h0, l0);
    split2(make_float2(v.z, v.w), h1, l1);
    *reinterpret_cast<uint2*>(buf + (size_t)row * 256 + col) = make_uint2(h0, h1);
    *reinterpret_cast<uint2*>(buf + (size_t)row * 256 + 128 + col) = make_uint2(l0, l1);
}

// smem layout: A[64 rows][512B + 16B pad], B[128 rows][512B + 16B pad], bias/csum/csq
#define LDKB 528
#define ASZ (64 * LDKB)             // 33792
#define SM_B_OFF ASZ
#define SM_BIAS (ASZ + 128 * LDKB)  // 101376
#define SM_CSUM (SM_BIAS + 512)
#define SM_CSQ (SM_BIAS + 1024)
#define SMEM_BYTES (SM_BIAS + 1536) // 102912 -> 2 CTAs/SM

// cp.async A tile: 64 rows x 512B (zfill beyond n)
__device__ __forceinline__ void load_Abf(uint32_t sA, const __nv_bfloat16* __restrict__ xb,
                                         int row0, int n, int t) {
#pragma unroll
    for (int j = 0; j < 8; j++) {
        int u = j * 256 + t;
        int row = u >> 5, c = u & 31;
        int gr = row0 + row;
        uint32_t sz = gr < n ? 16u : 0u;
        int gs = gr < n ? gr : 0;
        cpa16(sA + row * LDKB + c * 16, (const char*)xb + (size_t)gs * 512 + c * 16, sz);
    }
}
// cp.async B tile: 128 rows x 512B
__device__ __forceinline__ void load_Bbf(uint32_t sB, const __nv_bfloat16* __restrict__ wm,
                                         int t) {
#pragma unroll
    for (int j = 0; j < 16; j++) {
        int u = j * 256 + t;
        int row = u >> 5, c = u & 31;
        cpa16(sB + row * LDKB + c * 16, (const char*)wm + (size_t)row * 512 + c * 16, 16u);
    }
}

// mainloop: 8 k-steps, 3-term split (AhBh + AlBh + AhBl); warp grid 2(m) x 4(n)
__device__ __forceinline__ void mma_pass(uint32_t sA, uint32_t sB, float acc[2][4][4],
                                         int wm, int wn, int lane) {
    uint32_t a_base = sA + (uint32_t)(wm * 32 + (lane & 15)) * LDKB + (uint32_t)(lane >> 4) * 16;
    uint32_t b_base = sB + (uint32_t)(wn * 32 + (lane & 15)) * LDKB + (uint32_t)(lane >> 4) * 16;
#pragma unroll
    for (int ks = 0; ks < 8; ks++) {
        uint32_t kb = (uint32_t)ks * 32;
        uint32_t ah[2][4], al[2][4], bh[2][4], bl[2][4];
        ldsm4(a_base + kb, ah[0]);
        ldsm4(a_base + 16 * LDKB + kb, ah[1]);
        ldsm4(a_base + 256 + kb, al[0]);
        ldsm4(a_base + 16 * LDKB + 256 + kb, al[1]);
        ldsm4(b_base + kb, bh[0]);
        ldsm4(b_base + 16 * LDKB + kb, bh[1]);
        ldsm4(b_base + 256 + kb, bl[0]);
        ldsm4(b_base + 16 * LDKB + 256 + kb, bl[1]);
#pragma unroll
        for (int mt = 0; mt < 2; mt++)
#pragma unroll
            for (int nt = 0; nt < 4; nt++) {
                int nt2 = nt >> 1, p = nt & 1;
                mma16816(acc[mt][nt], ah[mt], bh[nt2][p], bh[nt2][p + 2]);
                mma16816(acc[mt][nt], al[mt], bh[nt2][p], bh[nt2][p + 2]);
                mma16816(acc[mt][nt], ah[mt], bl[nt2][p], bl[nt2][p + 2]);
            }
    }
}

// epilogue: bias, store y, column sum/sumsq via warp shfl + smem atomics
__device__ __forceinline__ void epilogue(float acc[2][4][4], float* __restrict__ y,
                                         const float* sbias, float* csum, float* csq,
                                         int row0, int n, int wm, int wn, int lane) {
    float ps[4][2], pq[4][2];
#pragma unroll
    for (int nt = 0; nt < 4; nt++) {
        ps[nt][0] = 0.f; ps[nt][1] = 0.f; pq[nt][0] = 0.f; pq[nt][1] = 0.f;
    }
    int mrow = row0 + wm * 32 + (lane >> 2);
#pragma unroll
    for (int mt = 0; mt < 2; mt++) {
#pragma unroll
        for (int h = 0; h < 2; h++) {
            int r = mrow + mt * 16 + h * 8;
            bool ok = r < n;
            float* yr = y + (size_t)r * D;
#pragma unroll
            for (int nt = 0; nt < 4; nt++) {
                int col = wn * 32 + nt * 8 + (lane & 3) * 2;
                float c0 = acc[mt][nt][h * 2 + 0] + sbias[col];
                float c1 = acc[mt][nt][h * 2 + 1] + sbias[col + 1];
                if (ok) {
                    *(float2*)(yr + col) = make_float2(c0, c1);
                    ps[nt][0] += c0; ps[nt][1] += c1;
                    pq[nt][0] += c0 * c0; pq[nt][1] += c1 * c1;
                }
            }
        }
    }
#pragma unroll
    for (int off = 16; off >= 4; off >>= 1) {
#pragma unroll
        for (int nt = 0; nt < 4; nt++) {
            ps[nt][0] += __shfl_xor_sync(0xffffffffu, ps[nt][0], off);
            ps[nt][1] += __shfl_xor_sync(0xffffffffu, ps[nt][1], off);
            pq[nt][0] += __shfl_xor_sync(0xffffffffu, pq[nt][0], off);
            pq[nt][1] += __shfl_xor_sync(0xffffffffu, pq[nt][1], off);
        }
    }
    if ((lane >> 2) == 0) {
#pragma unroll
        for (int nt = 0; nt < 4; nt++) {
            int col = wn * 32 + nt * 8 + (lane & 3) * 2;
            atomicAdd(&csum[col], ps[nt][0]);
            atomicAdd(&csum[col + 1], ps[nt][1]);
            atomicAdd(&csq[col], pq[nt][0]);
            atomicAdd(&csq[col + 1], pq[nt][1]);
        }
    }
}

// ---------------- weight pre-conversion: transpose + bf16 hi/lo split ----------------
__global__ void convw_kernel(const float* __restrict__ W, __nv_bfloat16* __restrict__ dst) {
    int bm = blockIdx.x;
    const float* Wk = W + (size_t)bm * 16384;
    __nv_bfloat16* ob = dst + (size_t)bm * 32768;
    int t = threadIdx.x;
    int f = t & 127;
    int d0 = (t >> 7) * 64;
#pragma unroll 4
    for (int jd = 0; jd < 64; jd += 4) {
        int d = d0 + jd;
        float w0 = Wk[(size_t)(d + 0) * D + f];
        float w1 = Wk[(size_t)(d + 1) * D + f];
        float w2 = Wk[(size_t)(d + 2) * D + f];
        float w3 = Wk[(size_t)(d + 3) * D + f];
        uint32_t h0, l0, h1, l1;
        split2(make_float2(w0, w1), h0, l0);
        split2(make_float2(w2, w3), h1, l1);
        *reinterpret_cast<uint2*>(ob + (size_t)f * 256 + d) = make_uint2(h0, h1);
        *reinterpret_cast<uint2*>(ob + (size_t)f * 256 + 128 + d) = make_uint2(l0, l1);
    }
}

// ---------------- GEMM (3 parallel N x 128 x 128), M=64 tiles ----------------
__global__ void __launch_bounds__(256) gemm3_tc_kernel(
    const __nv_bfloat16* __restrict__ x0, const __nv_bfloat16* __restrict__ x1,
    const __nv_bfloat16* __restrict__ x2, const __nv_bfloat16* __restrict__ wbase,
    const float* __restrict__ b, float* __restrict__ y, float* __restrict__ stats, int n) {
    extern __shared__ char sc[];
    uint32_t sbase = smem_u32(sc);
    float* sbias = (float*)(sc + SM_BIAS);
    float* csum = (float*)(sc + SM_CSUM);
    float* csq = (float*)(sc + SM_CSQ);

    const int t = threadIdx.x;
    const int wid = t >> 5, lane = t & 31;
    const int wm = wid & 1, wn = wid >> 1;
    const int kidx = blockIdx.y;
    const __nv_bfloat16* __restrict__ x = kidx == 0 ? x0 : (kidx == 1 ? x1 : x2);
    const int row0 = blockIdx.x * 64;

    load_Abf(sbase, x, row0, n, t);
    load_Bbf(sbase + SM_B_OFF, wbase + (size_t)kidx * 32768, t);
    CPCOMMIT();
    if (t < 128) {
        sbias[t] = b[kidx * D + t];
        csum[t] = 0.f;
        csq[t] = 0.f;
    }
    CPWAIT0();
    __syncthreads();

    float acc[2][4][4];
#pragma unroll
    for (int i = 0; i < 2; i++)
#pragma unroll
        for (int j = 0; j < 4; j++)
#pragma unroll
            for (int q = 0; q < 4; q++) acc[i][j][q] = 0.f;

    mma_pass(sbase, sbase + SM_B_OFF, acc, wm, wn, lane);

    epilogue(acc, y + (size_t)kidx * n * D, sbias, csum, csq, row0, n, wm, wn, lane);
    __syncthreads();
    if (t < 128) {
        atomicAdd(&stats[kidx * 256 + t], csum[t]);
        atomicAdd(&stats[kidx * 256 + 128 + t], csq[t]);
    }
}

// ---------------- concat GEMM (K = 3x128 from three sources), M=64 tiles ------------
__global__ void __launch_bounds__(256) gemmcat_tc_kernel(
    const __nv_bfloat16* __restrict__ x0, const __nv_bfloat16* __restrict__ x1,
    const __nv_bfloat16* __restrict__ x2, const __nv_bfloat16* __restrict__ wbase,
    const float* __restrict__ bc, float* __restrict__ y, float* __restrict__ stats, int n) {
    extern __shared__ char sc[];
    uint32_t sbase = smem_u32(sc);
    float* sbias = (float*)(sc + SM_BIAS);
    float* csum = (float*)(sc + SM_CSUM);
    float* csq = (float*)(sc + SM_CSQ);

    const int t = threadIdx.x;
    const int wid = t >> 5, lane = t & 31;
    const int wm = wid & 1, wn = wid >> 1;
    const int row0 = blockIdx.x * 64;

    if (t < 128) {
        sbias[t] = bc[t];
        csum[t] = 0.f;
        csq[t] = 0.f;
    }

    float acc[2][4][4];
#pragma unroll
    for (int i = 0; i < 2; i++)
#pragma unroll
        for (int j = 0; j < 4; j++)
#pragma unroll
            for (int q = 0; q < 4; q++) acc[i][j][q] = 0.f;

    for (int c = 0; c < 3; c++) {
        if (c) __syncthreads();
        const __nv_bfloat16* __restrict__ x = c == 0 ? x0 : (c == 1 ? x1 : x2);
        load_Abf(sbase, x, row0, n, t);
        load_Bbf(sbase + SM_B_OFF, wbase + (size_t)c * 32768, t);
        CPCOMMIT();
        CPWAIT0();
        __syncthreads();
        mma_pass(sbase, sbase + SM_B_OFF, acc, wm, wn, lane);
    }

    epilogue(acc, y, sbias, csum, csq, row0, n, wm, wn, lane);
    __syncthreads();
    if (t < 128) {
        atomicAdd(&stats[t], csum[t]);
        atomicAdd(&stats[128 + t], csq[t]);
    }
}

// ---------------- small utility kernels ----------------
__global__ void zerof_kernel(float* p, int nel) {
    int i = blockIdx.x * blockDim.x + threadIdx.x;
    if (i < nel) p[i] = 0.f;
}
__global__ void zeroi_kernel(int* p, int nel) {
    int i = blockIdx.x * blockDim.x + threadIdx.x;
    if (i < nel) p[i] = 0;
}
__global__ void copyi_kernel(const int* __restrict__ a, int* __restrict__ b, int nel) {
    int i = blockIdx.x * blockDim.x + threadIdx.x;
    if (i < nel) b[i] = a[i];
}
__global__ void hist_kernel(const int* __restrict__ ed, int* __restrict__ deg, int e) {
    int i = blockIdx.x * blockDim.x + threadIdx.x;
    if (i < e) atomicAdd(&deg[ed[i]], 1);
}
__global__ void scan_kernel(const int* __restrict__ deg, int* __restrict__ off, int n) {
    __shared__ int sm[1024];
    int t = threadIdx.x;
    int chunk = (n + 1023) >> 10;
    int beg = t * chunk;
    int end = min(beg + chunk, n);
    int s = 0;
    for (int i = beg; i < end; i++) s += deg[i];
    sm[t] = s;
    __syncthreads();
    for (int d = 1; d < 1024; d <<= 1) {
        int v = (t >= d) ? sm[t - d] : 0;
        __syncthreads();
        sm[t] += v;
        __syncthreads();
    }
    int pre = (t == 0) ? 0 : sm[t - 1];
    for (int i = beg; i < end; i++) { off[i] = pre; pre += deg[i]; }
    if (t == 1023) off[n] = sm[1023];
}
__global__ void scatter_kernel(const int* __restrict__ es, const int* __restrict__ ed,
                               int* __restrict__ pos, int* __restrict__ csr, int e) {
    int i = blockIdx.x * blockDim.x + threadIdx.x;
    if (i < e) {
        int p = atomicAdd(&pos[ed[i]], 1);
        csr[p] = es[i];
    }
}
// pre: cand0 = src_emb, cand1 = src - hr, cand2 = src * hr -> bf16 hi/lo buffers
__global__ void pre_kernel(const float* __restrict__ a, const float* __restrict__ b,
                           __nv_bfloat16* __restrict__ sb, __nv_bfloat16* __restrict__ c1,
                           __nv_bfloat16* __restrict__ c2, int tot4) {
    int i = blockIdx.x * blockDim.x + threadIdx.x;
    if (i >= tot4) return;
    int row = i >> 5, col = (i & 31) * 4;
    float4 va = reinterpret_cast<const float4*>(a)[i];
    float4 vb = reinterpret_cast<const float4*>(b)[i];
    write4(sb, row, col, va);
    write4(c1, row, col, make_float4(va.x - vb.x, va.y - vb.y, va.z - vb.z, va.w - vb.w));
    write4(c2, row, col, make_float4(va.x * vb.x, va.y * vb.y, va.z * vb.z, va.w * vb.w));
}

// ---------------- aggregation: warp per node, CSR, reads bf16 hi/lo ----------------
__global__ void agg_kernel(const __nv_bfloat16* __restrict__ hb, const int* __restrict__ off,
                           const int* __restrict__ csr, __nv_bfloat16* __restrict__ meanb,
                           __nv_bfloat16* __restrict__ maxb, int n) {
    int wid = (blockIdx.x * blockDim.x + threadIdx.x) >> 5;
    int lane = threadIdx.x & 31;
    if (wid >= n) return;
    int beg = off[wid], end = off[wid + 1];
    float NI = __int_as_float(0xff800000);
    float4 s = make_float4(0.f, 0.f, 0.f, 0.f);
    float4 m = make_float4(NI, NI, NI, NI);
    const uint2* hp = (const uint2*)hb;
    for (int e = beg; e < end; e++) {
        int src = csr[e];
        uint2 uh = hp[(size_t)src * 64 + lane];
        uint2 ul = hp[(size_t)src * 64 + 32 + lane];
        float2 f0 = __bfloat1622float2(*(__nv_bfloat162*)&uh.x);
        float2 f1 = __bfloat1622float2(*(__nv_bfloat162*)&uh.y);
        float2 g0 = __bfloat1622float2(*(__nv_bfloat162*)&ul.x);
        float2 g1 = __bfloat1622float2(*(__nv_bfloat162*)&ul.y);
        float vx = f0.x + g0.x, vy = f0.y + g0.y, vz = f1.x + g1.x, vw = f1.y + g1.y;
        s.x += vx; s.y += vy; s.z += vz; s.w += vw;
        m.x = fmaxf(m.x, vx); m.y = fmaxf(m.y, vy);
        m.z = fmaxf(m.z, vz); m.w = fmaxf(m.w, vw);
    }
    int deg = end - beg;
    float inv = (deg > 0) ? (1.0f / (float)deg) : 0.f;
    float4 mn = make_float4(s.x * inv, s.y * inv, s.z * inv, s.w * inv);
    float4 mx = (deg > 0) ? m : make_float4(0.f, 0.f, 0.f, 0.f);
    write4(meanb, wid, lane * 4, mn);
    write4(maxb, wid, lane * 4, mx);
}

// ---------------- normalization coefficient computation ----------------
__global__ void finalize_kernel(const float* __restrict__ stats, const float* __restrict__ g,
                                const float* __restrict__ be, float* __restrict__ coef,
                                int nk, float invN) {
    int i = blockIdx.x * 128 + threadIdx.x;
    if (i < nk * 128) {
        int k = i >> 7, d = i & 127;
        float s = stats[k * 256 + d];
        float q = stats[k * 256 + 128 + d];
        float mu = s * invN;
        float var = fmaxf(q * invN - mu * mu, 0.f);
        float a = rsqrtf(var + 1e-5f) * g[i];
        float c = be[i] - mu * a;
        coef[i] = a;
        coef[nk * 128 + i] = c;
    }
}

// ---------------- normalize + relu + weighted combine ----------------
// pin: fp32 partial to add (or null); pout: fp32 partial out (or null);
// hbout: bf16 hi/lo final out (or null)
__global__ void combine3_kernel(const float* __restrict__ y, int n,
                                const float* __restrict__ coef, const float* __restrict__ wv,
                                const float* __restrict__ pin, float* __restrict__ pout,
                                __nv_bfloat16* __restrict__ hbout) {
    __shared__ float sA[384], sC[384], sw[3];
    int t = threadIdx.x;
    for (int i = t; i < 384; i += blockDim.x) { sA[i] = coef[i]; sC[i] = coef[384 + i]; }
    if (t < 3) sw[t] = wv[t];
    __syncthreads();
    int tot4 = n * 32;
    int i = blockIdx.x * blockDim.x + t;
    if (i >= tot4) return;
    int col = (i * 4) & 127;
    int row = i >> 5;
    size_t stride = (size_t)n * 32;
    const float4* y4 = reinterpret_cast<const float4*>(y);
    float4 a0 = *reinterpret_cast<float4*>(&sA[col]);
    float4 c0 = *reinterpret_cast<float4*>(&sC[col]);
    float4 a1 = *reinterpret_cast<float4*>(&sA[128 + col]);
    float4 c1 = *reinterpret_cast<float4*>(&sC[128 + col]);
    float4 a2 = *reinterpret_cast<float4*>(&sA[256 + col]);
    float4 c2 = *reinterpret_cast<float4*>(&sC[256 + col]);
    float4 y0 = y4[i], y1 = y4[i + stride], y2 = y4[i + 2 * stride];
    float w0 = sw[0], w1 = sw[1], w2 = sw[2];
    float4 r;
    r.x = w0 * fmaxf(fmaf(y0.x, a0.x, c0.x), 0.f) + w1 * fmaxf(fmaf(y1.x, a1.x, c1.x), 0.f) +
          w2 * fmaxf(fmaf(y2.x, a2.x, c2.x), 0.f);
    r.y = w0 * fmaxf(fmaf(y0.y, a0.y, c0.y), 0.f) + w1 * fmaxf(fmaf(y1.y, a1.y, c1.y), 0.f) +
          w2 * fmaxf(fmaf(y2.y, a2.y, c2.y), 0.f);
    r.z = w0 * fmaxf(fmaf(y0.z, a0.z, c0.z), 0.f) + w1 * fmaxf(fmaf(y1.z, a1.z, c1.z), 0.f) +
          w2 * fmaxf(fmaf(y2.z, a2.z, c2.z), 0.f);
    r.w = w0 * fmaxf(fmaf(y0.w, a0.w, c0.w), 0.f) + w1 * fmaxf(fmaf(y1.w, a1.w, c1.w), 0.f) +
          w2 * fmaxf(fmaf(y2.w, a2.w, c2.w), 0.f);
    if (pin) {
        float4 p = reinterpret_cast<const float4*>(pin)[i];
        r.x += p.x; r.y += p.y; r.z += p.z; r.w += p.w;
    }
    if (pout) reinterpret_cast<float4*>(pout)[i] = r;
    if (hbout) write4(hbout, row, col, r);
}

__global__ void combinecat_kernel(const float* __restrict__ y, int n,
                                  const float* __restrict__ coef, float* __restrict__ out) {
    __shared__ float sA[128], sC[128];
    int t = threadIdx.x;
    if (t < 128) { sA[t] = coef[t]; sC[t] = coef[128 + t]; }
    __syncthreads();
    int tot4 = n * 32;
    int i = blockIdx.x * blockDim.x + t;
    if (i >= tot4) return;
    int col = (i * 4) & 127;
    float4 a = *reinterpret_cast<float4*>(&sA[col]);
    float4 c = *reinterpret_cast<float4*>(&sC[col]);
    float4 v = reinterpret_cast<const float4*>(y)[i];
    float4 r;
    r.x = fmaxf(fmaf(v.x, a.x, c.x), 0.f);
    r.y = fmaxf(fmaf(v.y, a.y, c.y), 0.f);
    r.z = fmaxf(fmaf(v.z, a.z, c.z), 0.f);
    r.w = fmaxf(fmaf(v.w, a.w, c.w), 0.f);
    reinterpret_cast<float4*>(out)[i] = r;
}

// ---------------- host orchestration ----------------
extern "C" void kernel_launch(void* const* d_in, const int* in_sizes, int n_in,
                              void* d_out, int out_size) {
    const float* src_emb = (const float*)d_in[0];
    const float* hr      = (const float*)d_in[1];
    const int*   edge_src = (const int*)d_in[2];
    const int*   edge_dst = (const int*)d_in[3];
    const float* w_zero  = (const float*)d_in[4];
    const float* w_first = (const float*)d_in[5];
    const float* w_mid   = (const float*)d_in[6];
    const float* w_last  = (const float*)d_in[7];
    const float* W_zero  = (const float*)d_in[8];
    const float* b_zero  = (const float*)d_in[9];
    const float* g_zero  = (const float*)d_in[10];
    const float* be_zero = (const float*)d_in[11];
    const float* W_first = (const float*)d_in[12];
    const float* b_first = (const float*)d_in[13];
    const float* g_first = (const float*)d_in[14];
    const float* be_first = (const float*)d_in[15];
    const float* W_mid   = (const float*)d_in[16];
    const float* b_mid   = (const float*)d_in[17];
    const float* g_mid   = (const float*)d_in[18];
    const float* be_mid  = (const float*)d_in[19];
    const float* W_last  = (const float*)d_in[20];
    const float* b_last  = (const float*)d_in[21];
    const float* g_last  = (const float*)d_in[22];
    const float* be_last = (const float*)d_in[23];
    const float* W_cat   = (const float*)d_in[24];
    const float* b_cat   = (const float*)d_in[25];
    const float* g_cat   = (const float*)d_in[26];
    const float* be_cat  = (const float*)d_in[27];

    const int n = in_sizes[0] / D;
    const int e = in_sizes[2];
    float* out = (float*)d_out;

    float *part, *yb, *stats, *coef;
    __nv_bfloat16 *sb, *hb0, *hb1, *hb2, *hb3, *mbb, *xbb, *wb;
    int *deg, *off, *pos, *csr;
    cudaGetSymbolAddress((void**)&part, g_part);
    cudaGetSymbolAddress((void**)&yb, g_y);
    cudaGetSymbolAddress((void**)&sb, g_sb);
    cudaGetSymbolAddress((void**)&hb0, g_hb0);
    cudaGetSymbolAddress((void**)&hb1, g_hb1);
    cudaGetSymbolAddress((void**)&hb2, g_hb2);
    cudaGetSymbolAddress((void**)&hb3, g_hb3);
    cudaGetSymbolAddress((void**)&mbb, g_mbb);
    cudaGetSymbolAddress((void**)&xbb, g_xbb);
    cudaGetSymbolAddress((void**)&wb, g_wb);
    cudaGetSymbolAddress((void**)&stats, g_stats);
    cudaGetSymbolAddress((void**)&coef, g_coef);
    cudaGetSymbolAddress((void**)&deg, g_deg);
    cudaGetSymbolAddress((void**)&off, g_off);
    cudaGetSymbolAddress((void**)&pos, g_pos);
    cudaGetSymbolAddress((void**)&csr, g_csr);

    cudaFuncSetAttribute(gemm3_tc_kernel, cudaFuncAttributeMaxDynamicSharedMemorySize,
                         SMEM_BYTES);
    cudaFuncSetAttribute(gemmcat_tc_kernel, cudaFuncAttributeMaxDynamicSharedMemorySize,
                         SMEM_BYTES);

    const int tot4 = n * 32;
    const int ewb = (tot4 + 255) / 256;
    const int gmb = (n + 63) / 64;
    const float invN = 1.0f / (float)n;

    // --- weight pre-conversion (27 matrices) ---
    convw_kernel<<<3, 256>>>(W_zero, wb);
    convw_kernel<<<9, 256>>>(W_first, wb + (size_t)3 * 32768);
    convw_kernel<<<6, 256>>>(W_mid, wb + (size_t)12 * 32768);
    convw_kernel<<<6, 256>>>(W_last, wb + (size_t)18 * 32768);
    convw_kernel<<<3, 256>>>(W_cat, wb + (size_t)24 * 32768);

    // --- CSR build ---
    zeroi_kernel<<<(n + 255) / 256, 256>>>(deg, n);
    hist_kernel<<<(e + 255) / 256, 256>>>(edge_dst, deg, e);
    scan_kernel<<<1, 1024>>>(deg, off, n);
    copyi_kernel<<<(n + 255) / 256, 256>>>(off, pos, n);
    scatter_kernel<<<(e + 255) / 256, 256>>>(edge_src, edge_dst, pos, csr, e);

    auto mixed = [&](const __nv_bfloat16* x0, const __nv_bfloat16* x1,
                     const __nv_bfloat16* x2, int wbidx, const float* bb, const float* gg,
                     const float* bbe, const float* wv, const float* pin, float* pout,
                     __nv_bfloat16* hbout) {
        zerof_kernel<<<3, 256>>>(stats, 768);
        dim3 grid(gmb, 3);
        gemm3_tc_kernel<<<grid, 256, SMEM_BYTES>>>(x0, x1, x2, wb + (size_t)wbidx * 32768,
                                                   bb, yb, stats, n);
        finalize_kernel<<<3, 128>>>(stats, gg, bbe, coef, 3, invN);
        combine3_kernel<<<ewb, 256>>>(yb, n, coef, wv, pin, pout, hbout);
    };
    auto agg = [&](const __nv_bfloat16* h) {
        agg_kernel<<<ewb, 256>>>(h, off, csr, mbb, xbb, n);
    };

    // --- zero op ---
    pre_kernel<<<ewb, 256>>>(src_emb, hr, sb, mbb, xbb, tot4);
    mixed(sb, mbb, xbb, 0, b_zero, g_zero, be_zero, w_zero, nullptr, nullptr, hb0);

    // --- s0 and s1 term 1 share agg(h_in) ---
    agg(hb0);
    mixed(hb0, mbb, xbb, 3, b_first, g_first, be_first, w_first, nullptr, nullptr, hb1);
    mixed(hb0, mbb, xbb, 6, b_first + 384, g_first + 384, be_first + 384, w_first + 3,
          nullptr, part, nullptr);
    agg(hb1);
    mixed(hb1, mbb, xbb, 9, b_first + 768, g_first + 768, be_first + 768, w_first + 6, part,
          nullptr, hb2);
    mixed(hb1, mbb, xbb, 12, b_mid, g_mid, be_mid, w_mid, nullptr, nullptr, hb3);
    agg(hb2);
    mixed(hb2, mbb, xbb, 15, b_mid + 384, g_mid + 384, be_mid + 384, w_mid + 3, nullptr,
          nullptr, hb0);
    agg(hb3);
    mixed(hb3, mbb, xbb, 18, b_last, g_last, be_last, w_last, nullptr, part, nullptr);
    agg(hb0);
    mixed(hb0, mbb, xbb, 21, b_last + 384, g_last + 384, be_last + 384, w_last + 3, part,
          nullptr, hb1);

    // --- concat GEMM + batchnorm + relu -> out ---
    zerof_kernel<<<2, 256>>>(stats, 512);
    gemmcat_tc_kernel<<<gmb, 256, SMEM_BYTES>>>(hb3, hb0, hb1, wb + (size_t)24 * 32768,
                                                b_cat, yb, stats, n);
    finalize_kernel<<<1, 128>>>(stats, g_cat, be_cat, coef, 1, invN);
    combinecat_kernel<<<ewb, 256>>>(yb, n, coef, out);
}